// round 12
// baseline (speedup 1.0000x reference)
#include <cuda_runtime.h>
#include <math.h>

#define BB 2
#define C  19
#define C2 20                      // padded channel stride (19 + 1 zero pad) -> 80B, float4-aligned
#define H  128
#define W  128
#define CH 320
#define CG 32
#define HW (H*W)
#define NPIX_BLK 256               // pixel blocks (one image row each)
#define NSIM_BLK (BB*CG)           // 64 simtab blocks (one coarse row each)
#define F32_FLUSH_THRESH 1.1754943508222875e-38   // FLT_MIN: emulate reference FTZ exp

// ---------------- scratch (__device__ globals; no allocation) ----------------
__device__ float  g_probT[BB * HW * C2];  // softmax, channel-contiguous (B,H,W,C2), pad=0
__device__ float  g_Sd[BB * CG * CG * 5]; // per coarse cell: E,SW,S,SE sims + oob sim
__device__ double g_pp[NPIX_BLK];         // per-block partial: sum loc_pos (masked)
__device__ double g_pn[NPIX_BLK];         // per-block partial: sum loc_neg (masked)
__device__ int    g_pm[NPIX_BLK];         // per-block partial: mask count

// ======== kernel 1: softmax (blocks 0..255) || directed sim table (256..319) ========
__global__ void __launch_bounds__(128) pre_k(const float* __restrict__ logits,
                                             const float* __restrict__ x_ema) {
    int blk = blockIdx.x;
    int t   = threadIdx.x;

    if (blk < NPIX_BLK) {
        // ---- softmax over C=19 for one image row; channel-contiguous output ----
        int b = blk >> 7, i = blk & 127;
        const float* base = logits + (size_t)b * C * HW + i * W + t;
        float v[C];
        float m = -INFINITY;
#pragma unroll
        for (int c = 0; c < C; c++) { v[c] = base[c * HW]; m = fmaxf(m, v[c]); }
        float s = 0.f;
#pragma unroll
        for (int c = 0; c < C; c++) { v[c] = expf(v[c] - m); s += v[c]; }
        float inv = 1.f / s;
        float4* o = (float4*)(g_probT + ((size_t)b * HW + i * W + t) * C2);
        o[0] = make_float4(v[0] * inv,  v[1] * inv,  v[2] * inv,  v[3] * inv);
        o[1] = make_float4(v[4] * inv,  v[5] * inv,  v[6] * inv,  v[7] * inv);
        o[2] = make_float4(v[8] * inv,  v[9] * inv,  v[10] * inv, v[11] * inv);
        o[3] = make_float4(v[12] * inv, v[13] * inv, v[14] * inv, v[15] * inv);
        o[4] = make_float4(v[16] * inv, v[17] * inv, v[18] * inv, 0.f);   // zero pad
    } else {
        // ---- directed coarse-cell sim table, one coarse row per block ----
        int cb = blk - NPIX_BLK;
        int b  = cb >> 5, ci = cb & 31;
        int g  = t >> 5, lane = t & 31;           // lane == cj
        const float* xb = x_ema + ((size_t)(b * CH) * CG + ci) * CG + lane;
        bool has_s = (ci < CG - 1);

        float a0 = 0.f, a1 = 0.f, a2 = 0.f, a3 = 0.f, a4 = 0.f;
#pragma unroll 8
        for (int ch = g; ch < CH; ch += 4) {
            float c  = xb[(size_t)ch * (CG * CG)];
            float sv = has_s ? xb[(size_t)ch * (CG * CG) + CG] : 0.f;
            float nE = __shfl_down_sync(0xffffffffu, c,  1);
            float sW = __shfl_up_sync  (0xffffffffu, sv, 1);
            float sE = __shfl_down_sync(0xffffffffu, sv, 1);
            float d0 = nE - c, d1 = sW - c, d2 = sv - c, d3 = sE - c;
            a0 += d0 * d0; a1 += d1 * d1; a2 += d2 * d2; a3 += d3 * d3; a4 += c * c;
        }
        __shared__ float red[4][32][5];
        red[g][lane][0] = a0; red[g][lane][1] = a1; red[g][lane][2] = a2;
        red[g][lane][3] = a3; red[g][lane][4] = a4;
        __syncthreads();
        {
            // 128 threads cover e=0..3 (one per warp); warp 0 also writes e=4.
            int cj = t & 31, e = t >> 5;
            float* cell_out = g_Sd + (size_t)((b * CG + ci) * CG + cj) * 5;
            float s = red[0][cj][e] + red[1][cj][e] + red[2][cj][e] + red[3][cj][e];
            double tt = exp(-(double)s * 0.25);      // FTZ-immune double exp
            if (tt < F32_FLUSH_THRESH) tt = 0.0;     // emulate reference FTZ
            cell_out[e] = (float)tt;
            if (e == 0) {
                float s4 = red[0][cj][4] + red[1][cj][4] + red[2][cj][4] + red[3][cj][4];
                double t4 = exp(-(double)s4 * 0.25);
                if (t4 < F32_FLUSH_THRESH) t4 = 0.0;
                cell_out[4] = (float)t4;
            }
        }
    }
}

// ======== kernel 2: per-pixel loss, 2 threads per pixel, NO atomics ========
// 256 threads: half 0 (t<128) computes neighbors k=0..4, half 1 k=5..8.
// Then half 0 does top-5 selection, half 1 does bottom-4, in parallel.
__global__ void __launch_bounds__(256) pixel_k(const float* __restrict__ x_ema) {
    __shared__ float4 rows[3][W * 5];       // prob rows i-2, i, i+2 (30720 B)
    __shared__ float  s_sim[W][9];          // exchanged per-pixel neighbor data
    __shared__ float  s_cp[W][9];
    __shared__ float  s_cn[W][9];
    __shared__ float  sr0[8], sr1[8];
    __shared__ int    sr2[8];

    int blk = blockIdx.x;
    int t   = threadIdx.x;
    int b = blk >> 7, i = blk & 127;
    int j    = t & 127;
    int half = t >> 7;

    const float4* PT4 = (const float4*)(g_probT + (size_t)b * HW * C2);

    // cooperative, coalesced load of the 3 needed rows into smem
#pragma unroll
    for (int r = 0; r < 3; r++) {
        int ni = i + (r - 1) * 2;
        if (ni >= 0 && ni < H) {
            const float4* src = PT4 + (size_t)ni * W * 5;
            for (int q = t; q < W * 5; q += 256)
                rows[r][q] = src[q];
        }
    }
    __syncthreads();

    // center pixel: sequential accumulation (c order preserved)
    float4 p4[5];
    float sum_p = 0.f;
#pragma unroll
    for (int r = 0; r < 5; r++) {
        p4[r] = rows[1][j * 5 + r];
        sum_p += p4[r].x; sum_p += p4[r].y; sum_p += p4[r].z; sum_p += p4[r].w;
    }

    int ci = i >> 2, cj = j >> 2;
    const float* Sb = g_Sd + (size_t)b * CG * CG * 5;
    float sim_oob = Sb[(ci * CG + cj) * 5 + 4];

    // each half computes its neighbor subset and publishes to smem
    int k_lo = half ? 5 : 0;
    int k_hi = half ? 9 : 5;
#pragma unroll
    for (int k = 0; k < 9; k++) {
        if (k < k_lo || k >= k_hi) continue;
        int a  = k / 3, b2 = k % 3;
        int ni = i + (a - 1) * 2;
        int nj = j + (b2 - 1) * 2;
        float sv, cpos, cneg;
        if (ni < 0 || ni >= H || nj < 0 || nj >= W) {
            sv = sim_oob; cpos = 0.f; cneg = 0.f;
        } else {
            const float4* Q4 = &rows[a][nj * 5];
            float cpv = 0.f, sq = 0.f;
#pragma unroll
            for (int r = 0; r < 5; r++) {
                float4 q = Q4[r];
                cpv += p4[r].x * q.x; sq += q.x;
                cpv += p4[r].y * q.y; sq += q.y;
                cpv += p4[r].z * q.z; sq += q.z;
                cpv += p4[r].w * q.w; sq += q.w;
            }
            cpos = cpv;
            cneg = sum_p * sq - cpv;
            int dci = (ni >> 2) - ci;
            int dcj = (nj >> 2) - cj;
            if ((dci | dcj) == 0)      sv = 1.0f;
            else if (dci < 0)          sv = Sb[((ci - 1) * CG + cj + dcj) * 5 + (2 - dcj)];
            else if (dci > 0)          sv = Sb[(ci * CG + cj) * 5 + (2 + dcj)];
            else if (dcj > 0)          sv = Sb[(ci * CG + cj) * 5 + 0];
            else                       sv = Sb[(ci * CG + cj - 1) * 5 + 0];
        }
        s_sim[j][k] = sv; s_cp[j][k] = cpos; s_cn[j][k] = cneg;
    }
    __syncthreads();

    // mask = feats[:,0,:,:] > 0  ==  x_ema[b,0,ci,cj] > 0
    bool msk = x_ema[(size_t)b * CH * CG * CG + ci * CG + cj] > 0.f;

    float mlp = 0.f, mln = 0.f;
    int   mc  = 0;
    if (half == 0) {
        // top-5 largest sims (stable: lowest index wins ties, like jax top_k)
        float sim[9], cp[9];
#pragma unroll
        for (int k = 0; k < 9; k++) { sim[k] = s_sim[j][k]; cp[k] = s_cp[j][k]; }
        float lpos = 0.f;
        bool used[9];
#pragma unroll
        for (int k = 0; k < 9; k++) used[k] = false;
#pragma unroll
        for (int tt = 0; tt < 5; tt++) {
            float bv = -1.f, bcp = 0.f; int sel = -1;
#pragma unroll
            for (int k = 0; k < 9; k++)
                if (!used[k] && sim[k] > bv) { bv = sim[k]; bcp = cp[k]; sel = k; }
#pragma unroll
            for (int k = 0; k < 9; k++) used[k] = used[k] || (k == sel);
            lpos += bv * (-bcp);
        }
        mlp = msk ? lpos : 0.f;
        mc  = msk ? 1 : 0;
    } else {
        // bottom-4 sims (stable lowest-index ties, like top_k(-sim))
        float sim[9], cn[9];
#pragma unroll
        for (int k = 0; k < 9; k++) { sim[k] = s_sim[j][k]; cn[k] = s_cn[j][k]; }
        float lneg = 0.f;
        bool used[9];
#pragma unroll
        for (int k = 0; k < 9; k++) used[k] = false;
#pragma unroll
        for (int tt = 0; tt < 4; tt++) {
            float bv = 2.f, bcn = 0.f; int sel = -1;
#pragma unroll
            for (int k = 0; k < 9; k++)
                if (!used[k] && sim[k] < bv) { bv = sim[k]; bcn = cn[k]; sel = k; }
#pragma unroll
            for (int k = 0; k < 9; k++) used[k] = used[k] || (k == sel);
            lneg += (1.f - bv) * (-bcn);
        }
        mln = msk ? lneg : 0.f;
    }

    // block reduce (8 warps), then ONE plain store per block (no atomics)
#pragma unroll
    for (int off = 16; off; off >>= 1) {
        mlp += __shfl_down_sync(0xffffffffu, mlp, off);
        mln += __shfl_down_sync(0xffffffffu, mln, off);
        mc  += __shfl_down_sync(0xffffffffu, mc,  off);
    }
    int lane = t & 31, wid = t >> 5;
    if (lane == 0) { sr0[wid] = mlp; sr1[wid] = mln; sr2[wid] = mc; }
    __syncthreads();
    if (t == 0) {
        double a0 = 0.0, a1 = 0.0; int a2 = 0;
#pragma unroll
        for (int w = 0; w < 8; w++) { a0 += sr0[w]; a1 += sr1[w]; a2 += sr2[w]; }
        g_pp[blk] = a0;
        g_pn[blk] = a1;
        g_pm[blk] = a2;
    }
}

// ======== kernel 3: deterministic final reduce (1 block) ========
__global__ void __launch_bounds__(256) final_k(float* __restrict__ out) {
    int t = threadIdx.x;
    double v0 = g_pp[t];
    double v1 = g_pn[t];
    int    m  = g_pm[t];
#pragma unroll
    for (int off = 16; off; off >>= 1) {
        v0 += __shfl_down_sync(0xffffffffu, v0, off);
        v1 += __shfl_down_sync(0xffffffffu, v1, off);
        m  += __shfl_down_sync(0xffffffffu, m,  off);
    }
    __shared__ double sd0[8], sd1[8];
    __shared__ int    si[8];
    int lane = t & 31, wid = t >> 5;
    if (lane == 0) { sd0[wid] = v0; sd1[wid] = v1; si[wid] = m; }
    __syncthreads();
    if (t == 0) {
        double a0 = 0.0, a1 = 0.0; int a2 = 0;
#pragma unroll
        for (int w = 0; w < 8; w++) { a0 += sd0[w]; a1 += sd1[w]; a2 += si[w]; }
        float nm = (float)a2;
        out[0] = (float)a0 / (nm * 5.0f);   // W_POS = 1
        out[1] = (float)a1 / (nm * 4.0f);   // W_NEG = 1
    }
}

// ---------------- launch ----------------
extern "C" void kernel_launch(void* const* d_in, const int* in_sizes, int n_in,
                              void* d_out, int out_size) {
    const float* logits = (const float*)d_in[0];  // (2,19,128,128)
    const float* x_ema  = (const float*)d_in[1];  // (2,320,32,32)
    // d_in[2] = img_trg, unused by the reference.
    float* out = (float*)d_out;

    pre_k<<<NPIX_BLK + NSIM_BLK, 128>>>(logits, x_ema);
    pixel_k<<<NPIX_BLK, 256>>>(x_ema);
    final_k<<<1, 256>>>(out);
}

// round 13
// speedup vs baseline: 1.1761x; 1.1761x over previous
#include <cuda_runtime.h>
#include <math.h>

#define BB 2
#define C  19
#define C2 20                      // padded channel stride (19 + 1 zero pad) -> 80B, float4-aligned
#define H  128
#define W  128
#define CH 320
#define CG 32
#define HW (H*W)
#define NPIX_BLK 256               // softmax / pixel blocks (one image row each)
#define NSIM_BLK (BB*CG)           // 64 simtab blocks (one coarse row each)
#define F32_FLUSH_THRESH 1.1754943508222875e-38   // FLT_MIN: emulate reference FTZ exp

// ---------------- scratch (__device__ globals; no allocation) ----------------
__device__ float    g_probT[BB * HW * C2];  // softmax, channel-contiguous (B,H,W,C2), pad=0
__device__ float    g_Sd[BB * CG * CG * 5]; // per coarse cell: E,SW,S,SE sims + oob sim
__device__ double   g_acc[2];
__device__ int      g_nmask;
__device__ unsigned g_done = 0;             // finalize ticket (wraps -> replay-safe)

// ======== kernel 1: softmax (blocks 0..255) || directed sim table (256..319) ========
__global__ void __launch_bounds__(128) pre_k(const float* __restrict__ logits,
                                             const float* __restrict__ x_ema) {
    int blk = blockIdx.x;
    int t   = threadIdx.x;
    if (blk == 0 && t == 0) { g_acc[0] = 0.0; g_acc[1] = 0.0; g_nmask = 0; }

    if (blk < NPIX_BLK) {
        // ---- softmax over C=19 for one image row; channel-contiguous output ----
        int b = blk >> 7, i = blk & 127;
        const float* base = logits + (size_t)b * C * HW + i * W + t;
        float v[C];
        float m = -INFINITY;
#pragma unroll
        for (int c = 0; c < C; c++) { v[c] = base[c * HW]; m = fmaxf(m, v[c]); }
        float s = 0.f;
#pragma unroll
        for (int c = 0; c < C; c++) { v[c] = expf(v[c] - m); s += v[c]; }
        float inv = 1.f / s;
        float4* o = (float4*)(g_probT + ((size_t)b * HW + i * W + t) * C2);
        o[0] = make_float4(v[0] * inv,  v[1] * inv,  v[2] * inv,  v[3] * inv);
        o[1] = make_float4(v[4] * inv,  v[5] * inv,  v[6] * inv,  v[7] * inv);
        o[2] = make_float4(v[8] * inv,  v[9] * inv,  v[10] * inv, v[11] * inv);
        o[3] = make_float4(v[12] * inv, v[13] * inv, v[14] * inv, v[15] * inv);
        o[4] = make_float4(v[16] * inv, v[17] * inv, v[18] * inv, 0.f);   // zero pad
    } else {
        // ---- directed coarse-cell sim table, one coarse row per block ----
        // lanes = 32 cells (coalesced); 4 warps split channels mod 4.
        // Neighbors via shfl; edge-lane garbage entries are never read by pixel_k.
        int cb = blk - NPIX_BLK;
        int b  = cb >> 5, ci = cb & 31;
        int g  = t >> 5, lane = t & 31;           // lane == cj
        const float* xb = x_ema + ((size_t)(b * CH) * CG + ci) * CG + lane;
        bool has_s = (ci < CG - 1);

        float a0 = 0.f, a1 = 0.f, a2 = 0.f, a3 = 0.f, a4 = 0.f;
#pragma unroll 4
        for (int ch = g; ch < CH; ch += 4) {
            float c  = xb[(size_t)ch * (CG * CG)];
            float sv = has_s ? xb[(size_t)ch * (CG * CG) + CG] : 0.f;
            float nE = __shfl_down_sync(0xffffffffu, c,  1);
            float sW = __shfl_up_sync  (0xffffffffu, sv, 1);
            float sE = __shfl_down_sync(0xffffffffu, sv, 1);
            float d0 = nE - c, d1 = sW - c, d2 = sv - c, d3 = sE - c;
            a0 += d0 * d0; a1 += d1 * d1; a2 += d2 * d2; a3 += d3 * d3; a4 += c * c;
        }
        __shared__ float red[4][32][5];
        red[g][lane][0] = a0; red[g][lane][1] = a1; red[g][lane][2] = a2;
        red[g][lane][3] = a3; red[g][lane][4] = a4;
        __syncthreads();
        {
            // 128 threads cover e=0..3 (one per warp); warp 0 also writes e=4.
            int cj = t & 31, e = t >> 5;
            float* cell_out = g_Sd + (size_t)((b * CG + ci) * CG + cj) * 5;
            float s = red[0][cj][e] + red[1][cj][e] + red[2][cj][e] + red[3][cj][e];
            double tt = exp(-(double)s * 0.25);      // FTZ-immune double exp
            if (tt < F32_FLUSH_THRESH) tt = 0.0;     // emulate reference FTZ
            cell_out[e] = (float)tt;
            if (e == 0) {
                float s4 = red[0][cj][4] + red[1][cj][4] + red[2][cj][4] + red[3][cj][4];
                double t4 = exp(-(double)s4 * 0.25);
                if (t4 < F32_FLUSH_THRESH) t4 = 0.0;
                cell_out[4] = (float)t4;
            }
        }
    }
}

// ======== kernel 2: per-pixel loss + fused finalize (PDL secondary) ========
__global__ void __launch_bounds__(128) pixel_k(const float* __restrict__ x_ema,
                                               float* __restrict__ out) {
    int blk = blockIdx.x;
    int t   = threadIdx.x;
    int b = blk >> 7, i = blk & 127;
    int j = t;
    int ci = i >> 2, cj = j >> 2;

    // ---- pre-sync work: independent of pre_k (overlaps with it via PDL) ----
    bool msk = x_ema[(size_t)b * CH * CG * CG + ci * CG + cj] > 0.f;

    // wait for pre_k (primary grid) completion before touching its outputs
    asm volatile("griddepcontrol.wait;" ::: "memory");

    const float* PT = g_probT + (size_t)b * HW * C2;

    // center pixel: 5 float4 loads; sequential accumulation (c order preserved)
    float4 p4[5];
    float sum_p = 0.f;
    {
        const float4* P4 = (const float4*)(PT + (size_t)(i * W + j) * C2);
#pragma unroll
        for (int r = 0; r < 5; r++) {
            p4[r] = P4[r];
            sum_p += p4[r].x; sum_p += p4[r].y; sum_p += p4[r].z; sum_p += p4[r].w;
        }
    }

    const float* Sb = g_Sd + (size_t)b * CG * CG * 5;
    float sim_oob = Sb[(ci * CG + cj) * 5 + 4];

    float sim[9], cp[9], cn[9];
#pragma unroll
    for (int k = 0; k < 9; k++) {
        int a  = k / 3, b2 = k % 3;
        int ni = i + (a - 1) * 2;
        int nj = j + (b2 - 1) * 2;
        if (ni < 0 || ni >= H || nj < 0 || nj >= W) {
            sim[k] = sim_oob; cp[k] = 0.f; cn[k] = 0.f;
        } else {
            const float4* Q4 = (const float4*)(PT + (size_t)(ni * W + nj) * C2);
            float cpos = 0.f, sq = 0.f;
#pragma unroll
            for (int r = 0; r < 5; r++) {
                float4 q = Q4[r];
                cpos += p4[r].x * q.x; sq += q.x;
                cpos += p4[r].y * q.y; sq += q.y;
                cpos += p4[r].z * q.z; sq += q.z;
                cpos += p4[r].w * q.w; sq += q.w;
            }
            cp[k] = cpos;
            cn[k] = sum_p * sq - cpos;
            int dci = (ni >> 2) - ci;
            int dcj = (nj >> 2) - cj;
            float sv;
            if ((dci | dcj) == 0)      sv = 1.0f;
            else if (dci < 0)          sv = Sb[((ci - 1) * CG + cj + dcj) * 5 + (2 - dcj)];
            else if (dci > 0)          sv = Sb[(ci * CG + cj) * 5 + (2 + dcj)];
            else if (dcj > 0)          sv = Sb[(ci * CG + cj) * 5 + 0];
            else                       sv = Sb[(ci * CG + cj - 1) * 5 + 0];
            sim[k] = sv;
        }
    }

    // top-5 largest sims (stable: lowest index wins ties, like jax top_k)
    float lpos = 0.f;
    {
        bool used[9];
#pragma unroll
        for (int k = 0; k < 9; k++) used[k] = false;
#pragma unroll
        for (int tt = 0; tt < 5; tt++) {
            float bv = -1.f, bcp = 0.f; int sel = -1;
#pragma unroll
            for (int k = 0; k < 9; k++)
                if (!used[k] && sim[k] > bv) { bv = sim[k]; bcp = cp[k]; sel = k; }
#pragma unroll
            for (int k = 0; k < 9; k++) used[k] = used[k] || (k == sel);
            lpos += bv * (-bcp);
        }
    }
    // bottom-4 sims (stable lowest-index ties, like top_k(-sim))
    float lneg = 0.f;
    {
        bool used[9];
#pragma unroll
        for (int k = 0; k < 9; k++) used[k] = false;
#pragma unroll
        for (int tt = 0; tt < 4; tt++) {
            float bv = 2.f, bcn = 0.f; int sel = -1;
#pragma unroll
            for (int k = 0; k < 9; k++)
                if (!used[k] && sim[k] < bv) { bv = sim[k]; bcn = cn[k]; sel = k; }
#pragma unroll
            for (int k = 0; k < 9; k++) used[k] = used[k] || (k == sel);
            lneg += (1.f - bv) * (-bcn);
        }
    }

    float mlp = msk ? lpos : 0.f;
    float mln = msk ? lneg : 0.f;
    int   mc  = msk ? 1 : 0;

    __shared__ float s0[4], s1[4];
    __shared__ int   s2[4];
#pragma unroll
    for (int off = 16; off; off >>= 1) {
        mlp += __shfl_down_sync(0xffffffffu, mlp, off);
        mln += __shfl_down_sync(0xffffffffu, mln, off);
        mc  += __shfl_down_sync(0xffffffffu, mc,  off);
    }
    int lane = t & 31, wid = t >> 5;
    if (lane == 0) { s0[wid] = mlp; s1[wid] = mln; s2[wid] = mc; }
    __syncthreads();
    if (t == 0) {
        double a0 = (double)s0[0] + s0[1] + s0[2] + s0[3];
        double a1 = (double)s1[0] + s1[1] + s1[2] + s1[3];
        int    a2 = s2[0] + s2[1] + s2[2] + s2[3];
        atomicAdd(&g_acc[0], a0);
        atomicAdd(&g_acc[1], a1);
        atomicAdd(&g_nmask, a2);
        __threadfence();
        unsigned old = atomicInc(&g_done, NPIX_BLK - 1);   // wraps to 0 -> replay-safe
        if (old == NPIX_BLK - 1) {
            double p0 = atomicAdd(&g_acc[0], 0.0);
            double p1 = atomicAdd(&g_acc[1], 0.0);
            int    nm = atomicAdd(&g_nmask, 0);
            out[0] = (float)p0 / ((float)nm * 5.0f);   // W_POS = 1
            out[1] = (float)p1 / ((float)nm * 4.0f);   // W_NEG = 1
        }
    }
}

// ---------------- launch (PDL: pixel_k overlaps pre_k's execution) ----------------
extern "C" void kernel_launch(void* const* d_in, const int* in_sizes, int n_in,
                              void* d_out, int out_size) {
    const float* logits = (const float*)d_in[0];  // (2,19,128,128)
    const float* x_ema  = (const float*)d_in[1];  // (2,320,32,32)
    // d_in[2] = img_trg, unused by the reference.
    float* out = (float*)d_out;

    pre_k<<<NPIX_BLK + NSIM_BLK, 128>>>(logits, x_ema);

    cudaLaunchConfig_t cfg = {};
    cfg.gridDim  = dim3(NPIX_BLK, 1, 1);
    cfg.blockDim = dim3(128, 1, 1);
    cfg.stream   = 0;   // same (legacy default) stream as pre_k
    cudaLaunchAttribute attr[1];
    attr[0].id = cudaLaunchAttributeProgrammaticStreamSerialization;
    attr[0].val.programmaticStreamSerializationAllowed = 1;
    cfg.attrs    = attr;
    cfg.numAttrs = 1;
    cudaLaunchKernelEx(&cfg, pixel_k, x_ema, out);
}

// round 14
// speedup vs baseline: 1.2117x; 1.0302x over previous
#include <cuda_runtime.h>
#include <math.h>

#define BB 2
#define C  19
#define H  128
#define W  128
#define CH 320
#define CG 32
#define HW (H*W)
#define NPIX_BLK 256               // fused blocks (one image row each)
#define NSIM_BLK (BB*CG)           // 64 simtab blocks (one coarse row each)
#define F32_FLUSH_THRESH 1.1754943508222875e-38   // FLT_MIN: emulate reference FTZ exp

// ---------------- scratch (__device__ globals; no allocation) ----------------
__device__ float    g_Sd[BB * CG * CG * 5]; // per coarse cell: E,SW,S,SE sims + oob sim
__device__ double   g_acc[2];
__device__ int      g_nmask;
__device__ unsigned g_done = 0;             // finalize ticket (wraps -> replay-safe)

// ======== kernel 1: directed coarse-cell sim table (primary grid) ========
__global__ void __launch_bounds__(128) simtab_k(const float* __restrict__ x_ema) {
    int blk = blockIdx.x;
    int t   = threadIdx.x;
    if (blk == 0 && t == 0) { g_acc[0] = 0.0; g_acc[1] = 0.0; g_nmask = 0; }

    int b  = blk >> 5, ci = blk & 31;
    int g  = t >> 5, lane = t & 31;           // lane == cj
    const float* xb = x_ema + ((size_t)(b * CH) * CG + ci) * CG + lane;
    bool has_s = (ci < CG - 1);

    float a0 = 0.f, a1 = 0.f, a2 = 0.f, a3 = 0.f, a4 = 0.f;
#pragma unroll 4
    for (int ch = g; ch < CH; ch += 4) {
        float c  = xb[(size_t)ch * (CG * CG)];
        float sv = has_s ? xb[(size_t)ch * (CG * CG) + CG] : 0.f;
        float nE = __shfl_down_sync(0xffffffffu, c,  1);
        float sW = __shfl_up_sync  (0xffffffffu, sv, 1);
        float sE = __shfl_down_sync(0xffffffffu, sv, 1);
        float d0 = nE - c, d1 = sW - c, d2 = sv - c, d3 = sE - c;
        a0 += d0 * d0; a1 += d1 * d1; a2 += d2 * d2; a3 += d3 * d3; a4 += c * c;
    }
    __shared__ float red[4][32][5];
    red[g][lane][0] = a0; red[g][lane][1] = a1; red[g][lane][2] = a2;
    red[g][lane][3] = a3; red[g][lane][4] = a4;
    __syncthreads();
    {
        // 128 threads cover e=0..3 (one per warp); warp 0 also writes e=4.
        int cj = t & 31, e = t >> 5;
        float* cell_out = g_Sd + (size_t)((b * CG + ci) * CG + cj) * 5;
        float s = red[0][cj][e] + red[1][cj][e] + red[2][cj][e] + red[3][cj][e];
        double tt = exp(-(double)s * 0.25);      // FTZ-immune double exp
        if (tt < F32_FLUSH_THRESH) tt = 0.0;     // emulate reference FTZ
        cell_out[e] = (float)tt;
        if (e == 0) {
            float s4 = red[0][cj][4] + red[1][cj][4] + red[2][cj][4] + red[3][cj][4];
            double t4 = exp(-(double)s4 * 0.25);
            if (t4 < F32_FLUSH_THRESH) t4 = 0.0;
            cell_out[4] = (float)t4;
        }
    }
}

// ======== kernel 2 (PDL secondary): softmax-in-smem (halo recompute) + pixel loss ========
// 256 threads, one image row per block. Softmax rows i-2, i, i+2 computed locally
// into smem (no global prob array). Two threads per pixel for the neighbor dots
// and the two selections (R12 structure). Atomic+ticket finalize (R8 structure).
__global__ void __launch_bounds__(256) fused_px(const float* __restrict__ logits,
                                                const float* __restrict__ x_ema,
                                                float* __restrict__ out) {
    __shared__ float4 rows[3][W * 5];       // prob rows i-2, i, i+2 (30720 B)
    __shared__ float  s_sim[W][9];          // per-pixel exchange between halves
    __shared__ float  s_cp[W][9];
    __shared__ float  s_cn[W][9];
    __shared__ float  sr0[8], sr1[8];
    __shared__ int    sr2[8];

    int blk = blockIdx.x;
    int t   = threadIdx.x;
    int b = blk >> 7, i = blk & 127;
    int j    = t & 127;
    int half = t >> 7;
    int ci = i >> 2, cj = j >> 2;

    // independent of the primary grid: mask load (overlaps simtab via PDL)
    bool msk = x_ema[(size_t)b * CH * CG * CG + ci * CG + cj] > 0.f;

    // ---- Phase A: softmax for the 3 needed rows, written to smem ----
    // 384 tasks (3 rows x 128 cols) over 256 threads.
    for (int task = t; task < 384; task += 256) {
        int r  = task >> 7;          // 0,1,2 -> rows i-2, i, i+2
        int jj = task & 127;
        int ni = i + (r - 1) * 2;
        if (ni >= 0 && ni < H) {
            const float* base = logits + (size_t)b * C * HW + ni * W + jj;
            float v[C];
            float m = -INFINITY;
#pragma unroll
            for (int c = 0; c < C; c++) { v[c] = base[c * HW]; m = fmaxf(m, v[c]); }
            float s = 0.f;
#pragma unroll
            for (int c = 0; c < C; c++) { v[c] = expf(v[c] - m); s += v[c]; }
            float inv = 1.f / s;
            float4* o = &rows[r][jj * 5];
            o[0] = make_float4(v[0] * inv,  v[1] * inv,  v[2] * inv,  v[3] * inv);
            o[1] = make_float4(v[4] * inv,  v[5] * inv,  v[6] * inv,  v[7] * inv);
            o[2] = make_float4(v[8] * inv,  v[9] * inv,  v[10] * inv, v[11] * inv);
            o[3] = make_float4(v[12] * inv, v[13] * inv, v[14] * inv, v[15] * inv);
            o[4] = make_float4(v[16] * inv, v[17] * inv, v[18] * inv, 0.f);  // zero pad
        }
    }

    // sim table ready? (primary grid complete => g_Sd + g_acc init visible)
    asm volatile("griddepcontrol.wait;" ::: "memory");
    __syncthreads();

    // ---- Phase B: per-pixel neighbor dots, split across the two halves ----
    float4 p4[5];
    float sum_p = 0.f;
#pragma unroll
    for (int r = 0; r < 5; r++) {
        p4[r] = rows[1][j * 5 + r];
        sum_p += p4[r].x; sum_p += p4[r].y; sum_p += p4[r].z; sum_p += p4[r].w;
    }

    const float* Sb = g_Sd + (size_t)b * CG * CG * 5;
    float sim_oob = Sb[(ci * CG + cj) * 5 + 4];

    int k_lo = half ? 5 : 0;
    int k_hi = half ? 9 : 5;
#pragma unroll
    for (int k = 0; k < 9; k++) {
        if (k < k_lo || k >= k_hi) continue;
        int a  = k / 3, b2 = k % 3;
        int ni = i + (a - 1) * 2;
        int nj = j + (b2 - 1) * 2;
        float sv, cpos, cneg;
        if (ni < 0 || ni >= H || nj < 0 || nj >= W) {
            sv = sim_oob; cpos = 0.f; cneg = 0.f;
        } else {
            const float4* Q4 = &rows[a][nj * 5];
            float cpv = 0.f, sq = 0.f;
#pragma unroll
            for (int r = 0; r < 5; r++) {
                float4 q = Q4[r];
                cpv += p4[r].x * q.x; sq += q.x;
                cpv += p4[r].y * q.y; sq += q.y;
                cpv += p4[r].z * q.z; sq += q.z;
                cpv += p4[r].w * q.w; sq += q.w;
            }
            cpos = cpv;
            cneg = sum_p * sq - cpv;
            int dci = (ni >> 2) - ci;
            int dcj = (nj >> 2) - cj;
            if ((dci | dcj) == 0)      sv = 1.0f;
            else if (dci < 0)          sv = Sb[((ci - 1) * CG + cj + dcj) * 5 + (2 - dcj)];
            else if (dci > 0)          sv = Sb[(ci * CG + cj) * 5 + (2 + dcj)];
            else if (dcj > 0)          sv = Sb[(ci * CG + cj) * 5 + 0];
            else                       sv = Sb[(ci * CG + cj - 1) * 5 + 0];
        }
        s_sim[j][k] = sv; s_cp[j][k] = cpos; s_cn[j][k] = cneg;
    }
    __syncthreads();

    // ---- Phase C: selections (half 0 = top-5, half 1 = bottom-4) ----
    float mlp = 0.f, mln = 0.f;
    int   mc  = 0;
    if (half == 0) {
        float sim[9], cp[9];
#pragma unroll
        for (int k = 0; k < 9; k++) { sim[k] = s_sim[j][k]; cp[k] = s_cp[j][k]; }
        float lpos = 0.f;
        bool used[9];
#pragma unroll
        for (int k = 0; k < 9; k++) used[k] = false;
#pragma unroll
        for (int tt = 0; tt < 5; tt++) {
            float bv = -1.f, bcp = 0.f; int sel = -1;
#pragma unroll
            for (int k = 0; k < 9; k++)
                if (!used[k] && sim[k] > bv) { bv = sim[k]; bcp = cp[k]; sel = k; }
#pragma unroll
            for (int k = 0; k < 9; k++) used[k] = used[k] || (k == sel);
            lpos += bv * (-bcp);
        }
        mlp = msk ? lpos : 0.f;
        mc  = msk ? 1 : 0;
    } else {
        float sim[9], cn[9];
#pragma unroll
        for (int k = 0; k < 9; k++) { sim[k] = s_sim[j][k]; cn[k] = s_cn[j][k]; }
        float lneg = 0.f;
        bool used[9];
#pragma unroll
        for (int k = 0; k < 9; k++) used[k] = false;
#pragma unroll
        for (int tt = 0; tt < 4; tt++) {
            float bv = 2.f, bcn = 0.f; int sel = -1;
#pragma unroll
            for (int k = 0; k < 9; k++)
                if (!used[k] && sim[k] < bv) { bv = sim[k]; bcn = cn[k]; sel = k; }
#pragma unroll
            for (int k = 0; k < 9; k++) used[k] = used[k] || (k == sel);
            lneg += (1.f - bv) * (-bcn);
        }
        mln = msk ? lneg : 0.f;
    }

    // ---- block reduce (8 warps) + atomic/ticket finalize ----
#pragma unroll
    for (int off = 16; off; off >>= 1) {
        mlp += __shfl_down_sync(0xffffffffu, mlp, off);
        mln += __shfl_down_sync(0xffffffffu, mln, off);
        mc  += __shfl_down_sync(0xffffffffu, mc,  off);
    }
    int lane = t & 31, wid = t >> 5;
    if (lane == 0) { sr0[wid] = mlp; sr1[wid] = mln; sr2[wid] = mc; }
    __syncthreads();
    if (t == 0) {
        double a0 = 0.0, a1 = 0.0; int a2 = 0;
#pragma unroll
        for (int w = 0; w < 8; w++) { a0 += sr0[w]; a1 += sr1[w]; a2 += sr2[w]; }
        atomicAdd(&g_acc[0], a0);
        atomicAdd(&g_acc[1], a1);
        atomicAdd(&g_nmask, a2);
        __threadfence();
        unsigned old = atomicInc(&g_done, NPIX_BLK - 1);   // wraps to 0 -> replay-safe
        if (old == NPIX_BLK - 1) {
            double p0 = atomicAdd(&g_acc[0], 0.0);
            double p1 = atomicAdd(&g_acc[1], 0.0);
            int    nm = atomicAdd(&g_nmask, 0);
            out[0] = (float)p0 / ((float)nm * 5.0f);   // W_POS = 1
            out[1] = (float)p1 / ((float)nm * 4.0f);   // W_NEG = 1
        }
    }
}

// ---------------- launch (simtab primary, fused_px overlapped via PDL) ----------------
extern "C" void kernel_launch(void* const* d_in, const int* in_sizes, int n_in,
                              void* d_out, int out_size) {
    const float* logits = (const float*)d_in[0];  // (2,19,128,128)
    const float* x_ema  = (const float*)d_in[1];  // (2,320,32,32)
    // d_in[2] = img_trg, unused by the reference.
    float* out = (float*)d_out;

    simtab_k<<<NSIM_BLK, 128>>>(x_ema);

    cudaLaunchConfig_t cfg = {};
    cfg.gridDim  = dim3(NPIX_BLK, 1, 1);
    cfg.blockDim = dim3(256, 1, 1);
    cfg.stream   = 0;   // same (legacy default) stream as simtab_k
    cudaLaunchAttribute attr[1];
    attr[0].id = cudaLaunchAttributeProgrammaticStreamSerialization;
    attr[0].val.programmaticStreamSerializationAllowed = 1;
    cfg.attrs    = attr;
    cfg.numAttrs = 1;
    cudaLaunchKernelEx(&cfg, fused_px, logits, x_ema, out);
}